// round 11
// baseline (speedup 1.0000x reference)
#include <cuda_runtime.h>
#include <cuda_fp16.h>
#include <math.h>
#include <stdint.h>

#define SLEN 2048
#define DM   1024
#define NHEAD 16
#define HD   64
#define BATCH 2
#define NROWS (BATCH*SLEN)   // 4096

// ---------------- scratch (device globals; no allocation allowed) ----------
__device__ __half g_xh[(size_t)NROWS*DM];          // x fp16
__device__ __half g_ah[(size_t)NROWS*DM];          // attn out fp16
__device__ __half g_wqh[(size_t)3*DM*DM];          // (32*W_qkv)^T hi [3072,1024]
__device__ __half g_wql[(size_t)3*DM*DM];          // lo
__device__ __half g_woh[(size_t)DM*DM];            // (32*W_out)^T hi
__device__ __half g_wol[(size_t)DM*DM];
// q/k/v fp16, layout [B*H][S][64]; k,v keep lo (B-side operands)
__device__ __half g_qh[(size_t)BATCH*NHEAD*SLEN*HD];
__device__ __half g_kh[(size_t)BATCH*NHEAD*SLEN*HD];
__device__ __half g_kl[(size_t)BATCH*NHEAD*SLEN*HD];
__device__ __half g_vh[(size_t)BATCH*NHEAD*SLEN*HD];
__device__ __half g_vl[(size_t)BATCH*NHEAD*SLEN*HD];

// ---------------- baseline-PTX helpers -------------------------------------
__device__ __forceinline__ uint32_t smem_u32(const void* p) {
    uint32_t a;
    asm("{ .reg .u64 t; cvta.to.shared.u64 t, %1; cvt.u32.u64 %0, t; }"
        : "=r"(a) : "l"(p));
    return a;
}
__device__ __forceinline__ void cp16(uint32_t s, const void* g) {
    asm volatile("cp.async.cg.shared.global [%0], [%1], 16;"
                 :: "r"(s), "l"(g) : "memory");
}
#define CP_COMMIT() asm volatile("cp.async.commit_group;" ::: "memory")
#define CP_WAIT2()  asm volatile("cp.async.wait_group 2;" ::: "memory")
#define CP_WAIT1()  asm volatile("cp.async.wait_group 1;" ::: "memory")
#define CP_WAIT0()  asm volatile("cp.async.wait_group 0;" ::: "memory")

__device__ __forceinline__ void ldsm4(uint32_t* r, uint32_t addr) {
    asm volatile("ldmatrix.sync.aligned.m8n8.x4.shared.b16 {%0,%1,%2,%3}, [%4];"
        : "=r"(r[0]), "=r"(r[1]), "=r"(r[2]), "=r"(r[3]) : "r"(addr));
}
__device__ __forceinline__ void ldsm4t(uint32_t* r, uint32_t addr) {
    asm volatile("ldmatrix.sync.aligned.m8n8.x4.trans.shared.b16 {%0,%1,%2,%3}, [%4];"
        : "=r"(r[0]), "=r"(r[1]), "=r"(r[2]), "=r"(r[3]) : "r"(addr));
}
// fp16 MMA, fp32 accumulate
__device__ __forceinline__ void mma_f16(float* d, const uint32_t* a,
                                        const uint32_t* b) {
    asm volatile("mma.sync.aligned.m16n8k16.row.col.f32.f16.f16.f32 "
        "{%0,%1,%2,%3}, {%4,%5,%6,%7}, {%8,%9}, {%0,%1,%2,%3};"
        : "+f"(d[0]), "+f"(d[1]), "+f"(d[2]), "+f"(d[3])
        : "r"(a[0]), "r"(a[1]), "r"(a[2]), "r"(a[3]), "r"(b[0]), "r"(b[1]));
}
// pack two fp32 -> half2 (first arg in low half)
__device__ __forceinline__ uint32_t packh(float lo, float hi) {
    __half2 h = __floats2half2_rn(lo, hi);
    return *reinterpret_cast<uint32_t*>(&h);
}

// exp2 via FFMA poly (no MUFU). z expected <= 0; clamped at -40.
__device__ __forceinline__ float fast_exp2(float z) {
    z = fmaxf(z, -40.f);
    const float km = z + 12582912.f;          // round-to-nearest int
    const int   ki = __float_as_int(km) - 0x4B400000;   // = round(z)
    const float f  = z - (km - 12582912.f);   // frac in [-0.5, 0.5]
    float p = 0.0013333558f;
    p = fmaf(p, f, 0.0096181815f);
    p = fmaf(p, f, 0.0555041087f);
    p = fmaf(p, f, 0.2402265069f);
    p = fmaf(p, f, 0.6931471806f);
    p = fmaf(p, f, 1.0f);
    return p * __int_as_float((ki + 127) << 23);
}

#define SCQ   0.18033688011112042f   // hd^-0.5 * log2(e), folded into Q
#define WSC   32.0f                  // W pre-scale (keeps W_lo in fp16 normal range)
#define IWSC  0.03125f

// ---------------------------------------------------------------------------
// Convert fp32 -> fp16 (activations; single precision level)
// ---------------------------------------------------------------------------
__global__ __launch_bounds__(256) void conv_x_kernel(
    const float* __restrict__ src, __half* __restrict__ dst, int n)
{
    int i = (blockIdx.x * 256 + threadIdx.x) * 4;
    if (i >= n) return;
    float4 v = *(const float4*)(src + i);
    uint2 o;
    o.x = packh(v.x, v.y);
    o.y = packh(v.z, v.w);
    *(uint2*)(dst + i) = o;
}

// ---------------------------------------------------------------------------
// Transpose + scale(x32) + split: W[1024, N] fp32 -> Wt_hi/lo [N, 1024] fp16
// ---------------------------------------------------------------------------
__global__ __launch_bounds__(256) void conv_wt_kernel(
    const float* __restrict__ W, __half* __restrict__ hi,
    __half* __restrict__ lo, int N)
{
    __shared__ float t[32][33];
    const int n0 = blockIdx.x * 32, k0 = blockIdx.y * 32;
    const int tx = threadIdx.x & 31, ty = threadIdx.x >> 5;
    #pragma unroll
    for (int i = 0; i < 4; i++)
        t[ty + i * 8][tx] = W[(size_t)(k0 + ty + i * 8) * N + n0 + tx];
    __syncthreads();
    #pragma unroll
    for (int i = 0; i < 4; i++) {
        const int n = n0 + ty + i * 8;
        const float v = t[tx][ty + i * 8] * WSC;
        __half h = __float2half_rn(v);
        hi[(size_t)n * DM + k0 + tx] = h;
        lo[(size_t)n * DM + k0 + tx] = __float2half_rn(v - __half2float(h));
    }
}

// ---------------------------------------------------------------------------
// HMMA fp16 2-product GEMM: D = A * (B_hi + B_lo)^T, 128x128 CTA tile,
// 8 warps in 2m x 4n grid (warp tile 64x32), m16n8k16, K-chunk 32, 3-stage
// single-sync cp.async pipeline (32 barriers instead of 64; 16 ldsm per
// 64 MMAs). Stage = 3 arrays x 128 rows x 80B = 30720B; 3 stages = 90KB
// -> 2 CTAs/SM (180KB).
// DO_QKV: fused RoPE + 1/32 rescale + fp16 scatter (q hi; k,v hi+lo).
// ---------------------------------------------------------------------------
#define GST   30720
#define GARR  10240
template<int DO_QKV>
__global__ __launch_bounds__(256, 2) void hmma_gemm_kernel(
    const __half* __restrict__ A,
    const __half* __restrict__ Bhi, const __half* __restrict__ Blo,
    const float* __restrict__ rc, const float* __restrict__ rs,
    float* __restrict__ outp)
{
    extern __shared__ char smem[];
    const uint32_t sb = smem_u32(smem);
    const int tid = threadIdx.x, lane = tid & 31, wid = tid >> 5;
    const int wm = wid >> 2, wn = wid & 3;     // 2m x 4n
    const int row0 = blockIdx.y * 128, col0 = blockIdx.x * 128;

    float acc[4][4][4];                        // [mt][nf][q]
    #pragma unroll
    for (int m = 0; m < 4; m++)
        #pragma unroll
        for (int n = 0; n < 4; n++)
            #pragma unroll
            for (int q = 0; q < 4; q++) acc[m][n][q] = 0.f;

    const int lrow = tid >> 1, kh = tid & 1;   // 128 rows x 2 half-rows
    const __half* ga[3];
    ga[0] = A   + (size_t)(row0 + lrow) * DM + kh * 16;
    ga[1] = Bhi + (size_t)(col0 + lrow) * DM + kh * 16;
    ga[2] = Blo + (size_t)(col0 + lrow) * DM + kh * 16;
    const uint32_t ldst = lrow * 80 + kh * 32;

    auto issue = [&](int c) {
        const uint32_t buf = sb + (c % 3) * GST;
        const int k0 = c * 32;
        #pragma unroll
        for (int a = 0; a < 3; a++) {
            cp16(buf + a * GARR + ldst,      ga[a] + k0);
            cp16(buf + a * GARR + ldst + 16, ga[a] + k0 + 8);
        }
    };

    issue(0); CP_COMMIT();
    issue(1); CP_COMMIT();

    const uint32_t aoff = (uint32_t)((wm * 64 + (lane & 15)) * 80
                        + (lane >> 4) * 16);
    const uint32_t boff = (uint32_t)(GARR
                        + (wn * 32 + (lane & 7) + ((lane >> 4) << 3)) * 80
                        + ((lane >> 3) & 1) * 16);

    for (int c = 0; c < 32; c++) {
        CP_WAIT1();
        __syncthreads();
        if (c + 2 < 32) issue(c + 2);
        CP_COMMIT();
        const uint32_t buf = sb + (c % 3) * GST;
        const uint32_t ab = buf + aoff;
        const uint32_t bb = buf + boff;
        #pragma unroll
        for (int ks = 0; ks < 2; ks++) {
            uint32_t ah[4][4];
            #pragma unroll
            for (int mt = 0; mt < 4; mt++)
                ldsm4(ah[mt], ab + mt * 16 * 80 + ks * 32);
            #pragma unroll
            for (int nf2 = 0; nf2 < 2; nf2++) {
                uint32_t bh4[4], bl4[4];
                ldsm4(bh4, bb + nf2 * 16 * 80 + ks * 32);
                ldsm4(bl4, bb + GARR + nf2 * 16 * 80 + ks * 32);
                #pragma unroll
                for (int mt = 0; mt < 4; mt++) {
                    mma_f16(acc[mt][2 * nf2],     ah[mt], bh4);
                    mma_f16(acc[mt][2 * nf2],     ah[mt], bl4);
                    mma_f16(acc[mt][2 * nf2 + 1], ah[mt], bh4 + 2);
                    mma_f16(acc[mt][2 * nf2 + 1], ah[mt], bl4 + 2);
                }
            }
        }
    }

    // ---------------- epilogue ----------------
    const int l4 = lane >> 2, l2 = (lane & 3) * 2;
    if (DO_QKV) {
        const int part = col0 >> 10;                 // 0=q, 1=k, 2=v
        const int bhead = (col0 & 1023) >> 6;
        __half* dhi = (part == 0) ? g_qh : (part == 1) ? g_kh : g_vh;
        __half* dlo = (part == 1) ? g_kl : g_vl;     // unused for q
        #pragma unroll
        for (int mt = 0; mt < 4; mt++) {
            #pragma unroll
            for (int rr = 0; rr < 2; rr++) {
                const int grow = row0 + wm * 64 + mt * 16 + l4 + rr * 8;
                const int b = grow >> 11, s = grow & 2047;
                const float* rcp = rc + s * 32;
                const float* rsp = rs + s * 32;
                #pragma unroll
                for (int nf = 0; nf < 4; nf++) {
                    const int hcol = wn * 32 + nf * 8 + l2;
                    const int head = bhead + (hcol >> 6);
                    const int d = hcol & 63;
                    const size_t obase =
                        ((size_t)(b * NHEAD + head) * SLEN + s) * HD;
                    const float v1 = acc[mt][nf][rr * 2 + 0];
                    const float v2 = acc[mt][nf][rr * 2 + 1];
                    float ox, oy;
                    if (part < 2) {
                        const int pi = d >> 1;
                        const float cth = rcp[pi], sth = rsp[pi];
                        ox = v1 * cth - v2 * sth;
                        oy = v1 * sth + v2 * cth;
                    } else {
                        ox = v1; oy = v2;
                    }
                    if (part == 0) {
                        ox *= (SCQ * IWSC); oy *= (SCQ * IWSC);
                        *(uint32_t*)(dhi + obase + d) = packh(ox, oy);
                    } else {
                        ox *= IWSC; oy *= IWSC;
                        const uint32_t hb = packh(ox, oy);
                        const __half2 h2 = *reinterpret_cast<const __half2*>(&hb);
                        const uint32_t lb = packh(ox - __half2float(__low2half(h2)),
                                                  oy - __half2float(__high2half(h2)));
                        *(uint32_t*)(dhi + obase + d) = hb;
                        *(uint32_t*)(dlo + obase + d) = lb;
                    }
                }
            }
        }
    } else {
        #pragma unroll
        for (int mt = 0; mt < 4; mt++) {
            #pragma unroll
            for (int rr = 0; rr < 2; rr++) {
                const int grow = row0 + wm * 64 + mt * 16 + l4 + rr * 8;
                float* op = outp + (size_t)grow * DM + col0 + wn * 32 + l2;
                #pragma unroll
                for (int nf = 0; nf < 4; nf++) {
                    float2 o;
                    o.x = acc[mt][nf][rr * 2 + 0] * IWSC;
                    o.y = acc[mt][nf][rr * 2 + 1] * IWSC;
                    *(float2*)(op + nf * 8) = o;
                }
            }
        }
    }
}

// ---------------------------------------------------------------------------
// HMMA fp16 FlashAttention: BM=128 queries, KN=128 keys/tile, 256 thr.
// QK: q @ (k_hi + k_lo) (2 products). PV: p @ (v_hi + v_lo).
// FFMA exp2 softmax; P stays in registers. Diagonal-tile skips (exact).
// smem: 5 tiles (Q, Kh, Kl, Vh, Vl) of 128 x 72 fp16 (144B stride).
// ---------------------------------------------------------------------------
#define FTILE 18432          // 128*72*2 bytes
__global__ __launch_bounds__(256) void flash_hmma_kernel()
{
    extern __shared__ char fsm[];
    const uint32_t sb = smem_u32(fsm);
    const uint32_t Qt = sb;
    const uint32_t Kh = sb + 1 * FTILE, Kl = sb + 2 * FTILE;
    const uint32_t Vh = sb + 3 * FTILE, Vl = sb + 4 * FTILE;

    const int tid = threadIdx.x, lane = tid & 31, w = tid >> 5;
    const int qb = gridDim.x - 1 - blockIdx.x;      // long CTAs first
    const int q0 = qb * 128, bh = blockIdx.y;
    const size_t base = (size_t)bh * SLEN * HD;

    const __half *qg  = g_qh + base + (size_t)q0 * HD;
    const __half *khg = g_kh + base, *klg = g_kl + base;
    const __half *vhg = g_vh + base, *vlg = g_vl + base;

    auto ldpair = [&](uint32_t dh, uint32_t dl,
                      const __half* gh, const __half* gl) {
        #pragma unroll
        for (int kk = 0; kk < 4; kk++) {
            const int c = tid + kk * 256;
            const int row = c >> 3, q8 = c & 7;
            cp16(dh + row * 144 + q8 * 16, gh + row * 64 + q8 * 8);
            cp16(dl + row * 144 + q8 * 16, gl + row * 64 + q8 * 8);
        }
    };
    auto ldone = [&](uint32_t d, const __half* g) {
        #pragma unroll
        for (int kk = 0; kk < 4; kk++) {
            const int c = tid + kk * 256;
            const int row = c >> 3, q8 = c & 7;
            cp16(d + row * 144 + q8 * 16, g + row * 64 + q8 * 8);
        }
    };

    ldone(Qt, qg);
    ldpair(Kh, Kl, khg, klg);
    CP_COMMIT();
    ldpair(Vh, Vl, vhg, vlg);
    CP_COMMIT();

    uint32_t qf[4][4];
    float oacc[8][4];
    #pragma unroll
    for (int j = 0; j < 8; j++)
        #pragma unroll
        for (int q = 0; q < 4; q++) oacc[j][q] = 0.f;
    float m0 = -1e30f, m1 = -1e30f, l0 = 0.f, l1 = 0.f;

    const int nkb = qb + 1;
    for (int kb = 0; kb < nkb; kb++) {
        const bool lastt = (kb == nkb - 1);
        CP_WAIT1();
        __syncthreads();
        if (kb == 0) {
            #pragma unroll
            for (int ks = 0; ks < 4; ks++) {
                const uint32_t a = (uint32_t)((w * 16 + (lane & 15)) * 144
                                 + (ks * 16 + (lane >> 4) * 8) * 2);
                ldsm4(qf[ks], Qt + a);
            }
        }
        // ---- S = Q @ (K_hi + K_lo)^T ----
        float sacc[16][4];
        #pragma unroll
        for (int j = 0; j < 16; j++)
            #pragma unroll
            for (int q = 0; q < 4; q++) sacc[j][q] = 0.f;
        #pragma unroll
        for (int ks = 0; ks < 4; ks++) {
            #pragma unroll
            for (int p = 0; p < 8; p++) {
                if (lastt && p > w) continue;        // fully-masked col group
                uint32_t kh4[4], kl4[4];
                const uint32_t a = (uint32_t)((p * 16 + (lane & 15)) * 144
                                 + (ks * 16 + (lane >> 4) * 8) * 2);
                ldsm4(kh4, Kh + a);
                ldsm4(kl4, Kl + a);
                uint32_t bh0[2] = {kh4[0], kh4[2]}, bh1[2] = {kh4[1], kh4[3]};
                uint32_t bl0[2] = {kl4[0], kl4[2]}, bl1[2] = {kl4[1], kl4[3]};
                mma_f16(sacc[2 * p],     qf[ks], bh0);
                mma_f16(sacc[2 * p],     qf[ks], bl0);
                mma_f16(sacc[2 * p + 1], qf[ks], bh1);
                mma_f16(sacc[2 * p + 1], qf[ks], bl1);
            }
        }
        __syncthreads();                 // all warps done reading K smem
        if (!lastt) {
            ldpair(Kh, Kl, khg + (size_t)(kb + 1) * 128 * HD,
                           klg + (size_t)(kb + 1) * 128 * HD);
            CP_COMMIT();
        }

        // ---- softmax (registers only; overlaps with K prefetch) ----
        if (lastt) {  // diagonal tile: mask col > row (tile-local, kb*128==q0)
            const int rl0 = w * 16 + (lane >> 2);
            #pragma unroll
            for (int j = 0; j < 16; j++) {
                const int c = j * 8 + (lane & 3) * 2;
                if (c     > rl0)     sacc[j][0] = -1e30f;
                if (c + 1 > rl0)     sacc[j][1] = -1e30f;
                if (c     > rl0 + 8) sacc[j][2] = -1e30f;
                if (c + 1 > rl0 + 8) sacc[j][3] = -1e30f;
            }
        }
        float rmx0 = -1e30f, rmx1 = -1e30f;
        #pragma unroll
        for (int j = 0; j < 16; j++) {
            rmx0 = fmaxf(rmx0, fmaxf(sacc[j][0], sacc[j][1]));
            rmx1 = fmaxf(rmx1, fmaxf(sacc[j][2], sacc[j][3]));
        }
        rmx0 = fmaxf(rmx0, __shfl_xor_sync(0xffffffffu, rmx0, 1));
        rmx0 = fmaxf(rmx0, __shfl_xor_sync(0xffffffffu, rmx0, 2));
        rmx1 = fmaxf(rmx1, __shfl_xor_sync(0xffffffffu, rmx1, 1));
        rmx1 = fmaxf(rmx1, __shfl_xor_sync(0xffffffffu, rmx1, 2));
        const float mn0 = fmaxf(m0, rmx0), mn1 = fmaxf(m1, rmx1);
        const float rs0 = fast_exp2(m0 - mn0), rs1 = fast_exp2(m1 - mn1);
        m0 = mn0; m1 = mn1;
        float sum0 = 0.f, sum1 = 0.f;
        #pragma unroll
        for (int j = 0; j < 16; j++) {
            sacc[j][0] = fast_exp2(sacc[j][0] - m0);
            sacc[j][1] = fast_exp2(sacc[j][1] - m0);
            sacc[j][2] = fast_exp2(sacc[j][2] - m1);
            sacc[j][3] = fast_exp2(sacc[j][3] - m1);
            sum0 += sacc[j][0] + sacc[j][1];
            sum1 += sacc[j][2] + sacc[j][3];
        }
        sum0 += __shfl_xor_sync(0xffffffffu, sum0, 1);
        sum0 += __shfl_xor_sync(0xffffffffu, sum0, 2);
        sum1 += __shfl_xor_sync(0xffffffffu, sum1, 1);
        sum1 += __shfl_xor_sync(0xffffffffu, sum1, 2);
        l0 = l0 * rs0 + sum0;
        l1 = l1 * rs1 + sum1;
        #pragma unroll
        for (int j = 0; j < 8; j++) {
            oacc[j][0] *= rs0; oacc[j][1] *= rs0;
            oacc[j][2] *= rs1; oacc[j][3] *= rs1;
        }

        // ---- O += P @ (V_hi + V_lo) ----
        if (!lastt) CP_WAIT1(); else CP_WAIT0();
        __syncthreads();
        #pragma unroll
        for (int ks = 0; ks < 8; ks++) {
            if (lastt && ks > w) continue;           // P ~ 0 beyond diagonal
            const float* s0 = sacc[2 * ks];
            const float* s1 = sacc[2 * ks + 1];
            uint32_t ph[4];
            ph[0] = packh(s0[0], s0[1]); ph[1] = packh(s0[2], s0[3]);
            ph[2] = packh(s1[0], s1[1]); ph[3] = packh(s1[2], s1[3]);
            #pragma unroll
            for (int p = 0; p < 4; p++) {
                uint32_t vh4[4], vl4[4];
                const uint32_t a = (uint32_t)((ks * 16 + (lane & 15)) * 144
                                 + (p * 16 + (lane >> 4) * 8) * 2);
                ldsm4t(vh4, Vh + a);
                ldsm4t(vl4, Vl + a);
                uint32_t bh0[2] = {vh4[0], vh4[1]}, bh1[2] = {vh4[2], vh4[3]};
                uint32_t bl0[2] = {vl4[0], vl4[1]}, bl1[2] = {vl4[2], vl4[3]};
                mma_f16(oacc[2 * p],     ph, bh0);
                mma_f16(oacc[2 * p],     ph, bl0);
                mma_f16(oacc[2 * p + 1], ph, bh1);
                mma_f16(oacc[2 * p + 1], ph, bl1);
            }
        }
        __syncthreads();                 // all warps done reading V smem
        if (!lastt) {
            ldpair(Vh, Vl, vhg + (size_t)(kb + 1) * 128 * HD,
                           vlg + (size_t)(kb + 1) * 128 * HD);
            CP_COMMIT();
        }
    }

    // ---- epilogue: normalize, write fp16 [B,S,D] ----
    const float inv0 = 1.f / l0, inv1 = 1.f / l1;
    const int b = bh >> 4, h = bh & 15;
    const int s0r = q0 + w * 16 + (lane >> 2);
    const size_t rowA = (size_t)(b * SLEN + s0r);
    const size_t rowB = rowA + 8;
    const int colb = h * 64 + (lane & 3) * 2;
    #pragma unroll
    for (int j = 0; j < 8; j++) {
        const int col = colb + j * 8;
        *(uint32_t*)(g_ah + rowA * DM + col) =
            packh(oacc[j][0] * inv0, oacc[j][1] * inv0);
        *(uint32_t*)(g_ah + rowB * DM + col) =
            packh(oacc[j][2] * inv1, oacc[j][3] * inv1);
    }
}

// ---------------------------------------------------------------------------
extern "C" void kernel_launch(void* const* d_in, const int* in_sizes, int n_in,
                              void* d_out, int out_size)
{
    const float* x    = (const float*)d_in[0];
    const float* rc   = (const float*)d_in[1];
    const float* rs   = (const float*)d_in[2];
    const float* Wqkv = (const float*)d_in[3];
    const float* Wout = (const float*)d_in[4];
    float* out = (float*)d_out;

    const size_t mma_sh   = 3 * GST;     // 92160
    const size_t flash_sh = 5 * FTILE;   // 92160
    cudaFuncSetAttribute(hmma_gemm_kernel<1>,
        cudaFuncAttributeMaxDynamicSharedMemorySize, (int)mma_sh);
    cudaFuncSetAttribute(hmma_gemm_kernel<0>,
        cudaFuncAttributeMaxDynamicSharedMemorySize, (int)mma_sh);
    cudaFuncSetAttribute(flash_hmma_kernel,
        cudaFuncAttributeMaxDynamicSharedMemorySize, (int)flash_sh);

    __half *xh, *ah, *wqh, *wql, *woh, *wol;
    cudaGetSymbolAddress((void**)&xh,  g_xh);
    cudaGetSymbolAddress((void**)&ah,  g_ah);
    cudaGetSymbolAddress((void**)&wqh, g_wqh);
    cudaGetSymbolAddress((void**)&wql, g_wql);
    cudaGetSymbolAddress((void**)&woh, g_woh);
    cudaGetSymbolAddress((void**)&wol, g_wol);

    // 1. converts / transposes
    conv_x_kernel<<<(NROWS * DM) / 1024, 256>>>(x, xh, NROWS * DM);
    conv_wt_kernel<<<dim3(96, 32), 256>>>(Wqkv, wqh, wql, 3 * DM);
    conv_wt_kernel<<<dim3(32, 32), 256>>>(Wout, woh, wol, DM);

    // 2. QKV GEMM (fp16 HMMA) + fused RoPE + scatter
    hmma_gemm_kernel<1><<<dim3(24, 32), 256, mma_sh>>>(
        xh, wqh, wql, rc, rs, nullptr);

    // 3. flash attention (fp16 HMMA) -> g_ah
    flash_hmma_kernel<<<dim3(SLEN / 128, BATCH * NHEAD), 256, flash_sh>>>();

    // 4. out-projection GEMM (fp16 HMMA)
    hmma_gemm_kernel<0><<<dim3(8, 32), 256, mma_sh>>>(
        ah, woh, wol, nullptr, nullptr, out);
}

// round 12
// speedup vs baseline: 1.0999x; 1.0999x over previous
#include <cuda_runtime.h>
#include <cuda_fp16.h>
#include <math.h>
#include <stdint.h>

#define SLEN 2048
#define DM   1024
#define NHEAD 16
#define HD   64
#define BATCH 2
#define NROWS (BATCH*SLEN)   // 4096

// ---------------- scratch (device globals; no allocation allowed) ----------
__device__ __half g_xh[(size_t)NROWS*DM];          // x fp16
__device__ __half g_ah[(size_t)NROWS*DM];          // attn out fp16
__device__ __half g_wqh[(size_t)3*DM*DM];          // (32*W_qkv)^T hi [3072,1024]
__device__ __half g_wql[(size_t)3*DM*DM];          // lo
__device__ __half g_woh[(size_t)DM*DM];            // (32*W_out)^T hi
__device__ __half g_wol[(size_t)DM*DM];
// q/k/v fp16, layout [B*H][S][64]; k keeps lo (B-side of QK)
__device__ __half g_qh[(size_t)BATCH*NHEAD*SLEN*HD];
__device__ __half g_kh[(size_t)BATCH*NHEAD*SLEN*HD];
__device__ __half g_kl[(size_t)BATCH*NHEAD*SLEN*HD];
__device__ __half g_vh[(size_t)BATCH*NHEAD*SLEN*HD];

// ---------------- baseline-PTX helpers -------------------------------------
__device__ __forceinline__ uint32_t smem_u32(const void* p) {
    uint32_t a;
    asm("{ .reg .u64 t; cvta.to.shared.u64 t, %1; cvt.u32.u64 %0, t; }"
        : "=r"(a) : "l"(p));
    return a;
}
__device__ __forceinline__ void cp16(uint32_t s, const void* g) {
    asm volatile("cp.async.cg.shared.global [%0], [%1], 16;"
                 :: "r"(s), "l"(g) : "memory");
}
#define CP_COMMIT() asm volatile("cp.async.commit_group;" ::: "memory")
#define CP_WAIT2()  asm volatile("cp.async.wait_group 2;" ::: "memory")
#define CP_WAIT1()  asm volatile("cp.async.wait_group 1;" ::: "memory")
#define CP_WAIT0()  asm volatile("cp.async.wait_group 0;" ::: "memory")

__device__ __forceinline__ void ldsm4(uint32_t* r, uint32_t addr) {
    asm volatile("ldmatrix.sync.aligned.m8n8.x4.shared.b16 {%0,%1,%2,%3}, [%4];"
        : "=r"(r[0]), "=r"(r[1]), "=r"(r[2]), "=r"(r[3]) : "r"(addr));
}
__device__ __forceinline__ void ldsm4t(uint32_t* r, uint32_t addr) {
    asm volatile("ldmatrix.sync.aligned.m8n8.x4.trans.shared.b16 {%0,%1,%2,%3}, [%4];"
        : "=r"(r[0]), "=r"(r[1]), "=r"(r[2]), "=r"(r[3]) : "r"(addr));
}
// fp16 MMA, fp32 accumulate
__device__ __forceinline__ void mma_f16(float* d, const uint32_t* a,
                                        const uint32_t* b) {
    asm volatile("mma.sync.aligned.m16n8k16.row.col.f32.f16.f16.f32 "
        "{%0,%1,%2,%3}, {%4,%5,%6,%7}, {%8,%9}, {%0,%1,%2,%3};"
        : "+f"(d[0]), "+f"(d[1]), "+f"(d[2]), "+f"(d[3])
        : "r"(a[0]), "r"(a[1]), "r"(a[2]), "r"(a[3]), "r"(b[0]), "r"(b[1]));
}
// pack two fp32 -> half2 (first arg in low half)
__device__ __forceinline__ uint32_t packh(float lo, float hi) {
    __half2 h = __floats2half2_rn(lo, hi);
    return *reinterpret_cast<uint32_t*>(&h);
}

// exp2 via FFMA poly (no MUFU). z expected <= 0; clamped at -40.
__device__ __forceinline__ float fast_exp2(float z) {
    z = fmaxf(z, -40.f);
    const float km = z + 12582912.f;          // round-to-nearest int
    const int   ki = __float_as_int(km) - 0x4B400000;   // = round(z)
    const float f  = z - (km - 12582912.f);   // frac in [-0.5, 0.5]
    float p = 0.0013333558f;
    p = fmaf(p, f, 0.0096181815f);
    p = fmaf(p, f, 0.0555041087f);
    p = fmaf(p, f, 0.2402265069f);
    p = fmaf(p, f, 0.6931471806f);
    p = fmaf(p, f, 1.0f);
    return p * __int_as_float((ki + 127) << 23);
}

#define SCQ   0.18033688011112042f   // hd^-0.5 * log2(e), folded into Q
#define WSC   32.0f                  // W pre-scale (keeps W_lo in fp16 normal range)
#define IWSC  0.03125f

// ---------------------------------------------------------------------------
// Convert fp32 -> fp16 (activations; single precision level)
// ---------------------------------------------------------------------------
__global__ __launch_bounds__(256) void conv_x_kernel(
    const float* __restrict__ src, __half* __restrict__ dst, int n)
{
    int i = (blockIdx.x * 256 + threadIdx.x) * 4;
    if (i >= n) return;
    float4 v = *(const float4*)(src + i);
    uint2 o;
    o.x = packh(v.x, v.y);
    o.y = packh(v.z, v.w);
    *(uint2*)(dst + i) = o;
}

// ---------------------------------------------------------------------------
// Transpose + scale(x32) + split: W[1024, N] fp32 -> Wt_hi/lo [N, 1024] fp16
// ---------------------------------------------------------------------------
__global__ __launch_bounds__(256) void conv_wt_kernel(
    const float* __restrict__ W, __half* __restrict__ hi,
    __half* __restrict__ lo, int N)
{
    __shared__ float t[32][33];
    const int n0 = blockIdx.x * 32, k0 = blockIdx.y * 32;
    const int tx = threadIdx.x & 31, ty = threadIdx.x >> 5;
    #pragma unroll
    for (int i = 0; i < 4; i++)
        t[ty + i * 8][tx] = W[(size_t)(k0 + ty + i * 8) * N + n0 + tx];
    __syncthreads();
    #pragma unroll
    for (int i = 0; i < 4; i++) {
        const int n = n0 + ty + i * 8;
        const float v = t[tx][ty + i * 8] * WSC;
        __half h = __float2half_rn(v);
        hi[(size_t)n * DM + k0 + tx] = h;
        lo[(size_t)n * DM + k0 + tx] = __float2half_rn(v - __half2float(h));
    }
}

// ---------------------------------------------------------------------------
// HMMA fp16 2-product GEMM: D = A * (B_hi + B_lo)^T (round-10 config).
// 128x128 CTA tile, 8 warps (4m x 2n), m16n8k16, K-chunk 16, 4-stage
// single-sync cp.async pipeline. Stage = 3 arrays x 128 rows x 48B; 72KB ->
// 2 CTAs/SM.
// DO_QKV: fused RoPE + 1/32 rescale + fp16 scatter (q,v hi; k hi+lo).
// ---------------------------------------------------------------------------
#define GST   18432
#define GARR  6144
template<int DO_QKV>
__global__ __launch_bounds__(256, 2) void hmma_gemm_kernel(
    const __half* __restrict__ A,
    const __half* __restrict__ Bhi, const __half* __restrict__ Blo,
    const float* __restrict__ rc, const float* __restrict__ rs,
    float* __restrict__ outp)
{
    extern __shared__ char smem[];
    const uint32_t sb = smem_u32(smem);
    const int tid = threadIdx.x, lane = tid & 31, wid = tid >> 5;
    const int wm = wid >> 1, wn = wid & 1;
    const int row0 = blockIdx.y * 128, col0 = blockIdx.x * 128;

    float acc[2][8][4];
    #pragma unroll
    for (int m = 0; m < 2; m++)
        #pragma unroll
        for (int n = 0; n < 8; n++)
            #pragma unroll
            for (int q = 0; q < 4; q++) acc[m][n][q] = 0.f;

    const int lrow = tid >> 1, kh = tid & 1;
    const __half* ga[3];
    ga[0] = A   + (size_t)(row0 + lrow) * DM + kh * 8;
    ga[1] = Bhi + (size_t)(col0 + lrow) * DM + kh * 8;
    ga[2] = Blo + (size_t)(col0 + lrow) * DM + kh * 8;
    const uint32_t ldst = lrow * 48 + kh * 16;

    auto issue = [&](int c) {
        const uint32_t buf = sb + (c & 3) * GST;
        const int k0 = c * 16;
        #pragma unroll
        for (int a = 0; a < 3; a++)
            cp16(buf + a * GARR + ldst, ga[a] + k0);
    };

    issue(0); CP_COMMIT();
    issue(1); CP_COMMIT();
    issue(2); CP_COMMIT();

    const uint32_t aoff = (uint32_t)((wm * 32 + (lane & 15)) * 48
                        + (lane >> 4) * 16);
    const uint32_t boff = (uint32_t)(GARR
                        + (wn * 64 + (lane & 7) + ((lane >> 4) << 3)) * 48
                        + ((lane >> 3) & 1) * 16);

    for (int c = 0; c < 64; c++) {
        CP_WAIT2();
        __syncthreads();
        if (c + 3 < 64) issue(c + 3);
        CP_COMMIT();
        const uint32_t buf = sb + (c & 3) * GST;
        const uint32_t ab = buf + aoff;
        const uint32_t bb = buf + boff;
        uint32_t ah[2][4];
        ldsm4(ah[0], ab);
        ldsm4(ah[1], ab + 16 * 48);
        #pragma unroll
        for (int nf2 = 0; nf2 < 4; nf2++) {
            uint32_t bh4[4], bl4[4];
            ldsm4(bh4, bb + nf2 * 16 * 48);
            ldsm4(bl4, bb + GARR + nf2 * 16 * 48);
            #pragma unroll
            for (int mt = 0; mt < 2; mt++) {
                mma_f16(acc[mt][2 * nf2],     ah[mt], bh4);
                mma_f16(acc[mt][2 * nf2],     ah[mt], bl4);
                mma_f16(acc[mt][2 * nf2 + 1], ah[mt], bh4 + 2);
                mma_f16(acc[mt][2 * nf2 + 1], ah[mt], bl4 + 2);
            }
        }
    }

    // ---------------- epilogue ----------------
    const int l4 = lane >> 2, l2 = (lane & 3) * 2;
    if (DO_QKV) {
        const int part = col0 >> 10;                 // 0=q, 1=k, 2=v
        const int head = ((col0 & 1023) >> 6) + wn;
        __half* dhi = (part == 0) ? g_qh : (part == 1) ? g_kh : g_vh;
        #pragma unroll
        for (int mt = 0; mt < 2; mt++) {
            #pragma unroll
            for (int rr = 0; rr < 2; rr++) {
                const int grow = row0 + wm * 32 + mt * 16 + l4 + rr * 8;
                const int b = grow >> 11, s = grow & 2047;
                const size_t obase = ((size_t)(b * NHEAD + head) * SLEN + s) * HD;
                const float* rcp = rc + s * 32;
                const float* rsp = rs + s * 32;
                #pragma unroll
                for (int nf = 0; nf < 8; nf++) {
                    const int d = nf * 8 + l2;
                    const float v1 = acc[mt][nf][rr * 2 + 0];
                    const float v2 = acc[mt][nf][rr * 2 + 1];
                    float ox, oy;
                    if (part < 2) {
                        const int pi = d >> 1;
                        const float cth = rcp[pi], sth = rsp[pi];
                        ox = v1 * cth - v2 * sth;
                        oy = v1 * sth + v2 * cth;
                    } else {
                        ox = v1; oy = v2;
                    }
                    if (part == 1) {
                        ox *= IWSC; oy *= IWSC;
                        const uint32_t hb = packh(ox, oy);
                        const __half2 h2 = *reinterpret_cast<const __half2*>(&hb);
                        const uint32_t lb = packh(ox - __half2float(__low2half(h2)),
                                                  oy - __half2float(__high2half(h2)));
                        *(uint32_t*)(dhi + obase + d) = hb;
                        *(uint32_t*)(g_kl + obase + d) = lb;
                    } else {
                        const float sc = (part == 0) ? (SCQ * IWSC) : IWSC;
                        ox *= sc; oy *= sc;
                        *(uint32_t*)(dhi + obase + d) = packh(ox, oy);
                    }
                }
            }
        }
    } else {
        #pragma unroll
        for (int mt = 0; mt < 2; mt++) {
            #pragma unroll
            for (int rr = 0; rr < 2; rr++) {
                const int grow = row0 + wm * 32 + mt * 16 + l4 + rr * 8;
                float* op = outp + (size_t)grow * DM + col0 + wn * 64 + l2;
                #pragma unroll
                for (int nf = 0; nf < 8; nf++) {
                    float2 o;
                    o.x = acc[mt][nf][rr * 2 + 0] * IWSC;
                    o.y = acc[mt][nf][rr * 2 + 1] * IWSC;
                    *(float2*)(op + nf * 8) = o;
                }
            }
        }
    }
}

// ---------------------------------------------------------------------------
// HMMA fp16 FlashAttention: BM=128 queries, KN=128 keys/tile, 256 thr.
// QK: q @ (k_hi + k_lo) (2 MMAs). PV: p @ v_hi (1 MMA). FFMA exp2 softmax;
// P stays in registers. Diagonal-tile skips (exact).
// smem: 4 tiles (Q, Kh, Kl, Vh) of 128 x 72 fp16 (144B stride).
// ---------------------------------------------------------------------------
#define FTILE 18432          // 128*72*2 bytes
__global__ __launch_bounds__(256) void flash_hmma_kernel()
{
    extern __shared__ char fsm[];
    const uint32_t sb = smem_u32(fsm);
    const uint32_t Qt = sb;
    const uint32_t Kh = sb + 1 * FTILE, Kl = sb + 2 * FTILE;
    const uint32_t Vh = sb + 3 * FTILE;

    const int tid = threadIdx.x, lane = tid & 31, w = tid >> 5;
    const int qb = gridDim.x - 1 - blockIdx.x;      // long CTAs first
    const int q0 = qb * 128, bh = blockIdx.y;
    const size_t base = (size_t)bh * SLEN * HD;

    const __half *qg  = g_qh + base + (size_t)q0 * HD;
    const __half *khg = g_kh + base, *klg = g_kl + base;
    const __half *vhg = g_vh + base;

    auto ldpair = [&](uint32_t dh, uint32_t dl,
                      const __half* gh, const __half* gl) {
        #pragma unroll
        for (int kk = 0; kk < 4; kk++) {
            const int c = tid + kk * 256;
            const int row = c >> 3, q8 = c & 7;
            cp16(dh + row * 144 + q8 * 16, gh + row * 64 + q8 * 8);
            cp16(dl + row * 144 + q8 * 16, gl + row * 64 + q8 * 8);
        }
    };
    auto ldone = [&](uint32_t d, const __half* g) {
        #pragma unroll
        for (int kk = 0; kk < 4; kk++) {
            const int c = tid + kk * 256;
            const int row = c >> 3, q8 = c & 7;
            cp16(d + row * 144 + q8 * 16, g + row * 64 + q8 * 8);
        }
    };

    ldone(Qt, qg);
    ldpair(Kh, Kl, khg, klg);
    CP_COMMIT();
    ldone(Vh, vhg);
    CP_COMMIT();

    uint32_t qf[4][4];
    float oacc[8][4];
    #pragma unroll
    for (int j = 0; j < 8; j++)
        #pragma unroll
        for (int q = 0; q < 4; q++) oacc[j][q] = 0.f;
    float m0 = -1e30f, m1 = -1e30f, l0 = 0.f, l1 = 0.f;

    const int nkb = qb + 1;
    for (int kb = 0; kb < nkb; kb++) {
        const bool lastt = (kb == nkb - 1);
        CP_WAIT1();
        __syncthreads();
        if (kb == 0) {
            #pragma unroll
            for (int ks = 0; ks < 4; ks++) {
                const uint32_t a = (uint32_t)((w * 16 + (lane & 15)) * 144
                                 + (ks * 16 + (lane >> 4) * 8) * 2);
                ldsm4(qf[ks], Qt + a);
            }
        }
        // ---- S = Q @ (K_hi + K_lo)^T ----
        float sacc[16][4];
        #pragma unroll
        for (int j = 0; j < 16; j++)
            #pragma unroll
            for (int q = 0; q < 4; q++) sacc[j][q] = 0.f;
        #pragma unroll
        for (int ks = 0; ks < 4; ks++) {
            #pragma unroll
            for (int p = 0; p < 8; p++) {
                if (lastt && p > w) continue;        // fully-masked col group
                uint32_t kh4[4], kl4[4];
                const uint32_t a = (uint32_t)((p * 16 + (lane & 15)) * 144
                                 + (ks * 16 + (lane >> 4) * 8) * 2);
                ldsm4(kh4, Kh + a);
                ldsm4(kl4, Kl + a);
                uint32_t bh0[2] = {kh4[0], kh4[2]}, bh1[2] = {kh4[1], kh4[3]};
                uint32_t bl0[2] = {kl4[0], kl4[2]}, bl1[2] = {kl4[1], kl4[3]};
                mma_f16(sacc[2 * p],     qf[ks], bh0);
                mma_f16(sacc[2 * p],     qf[ks], bl0);
                mma_f16(sacc[2 * p + 1], qf[ks], bh1);
                mma_f16(sacc[2 * p + 1], qf[ks], bl1);
            }
        }
        __syncthreads();                 // all warps done reading K smem
        if (!lastt) {
            ldpair(Kh, Kl, khg + (size_t)(kb + 1) * 128 * HD,
                           klg + (size_t)(kb + 1) * 128 * HD);
            CP_COMMIT();
        }

        // ---- softmax (registers only; overlaps with K prefetch) ----
        if (lastt) {  // diagonal tile: mask col > row (tile-local, kb*128==q0)
            const int rl0 = w * 16 + (lane >> 2);
            #pragma unroll
            for (int j = 0; j < 16; j++) {
                const int c = j * 8 + (lane & 3) * 2;
                if (c     > rl0)     sacc[j][0] = -1e30f;
                if (c + 1 > rl0)     sacc[j][1] = -1e30f;
                if (c     > rl0 + 8) sacc[j][2] = -1e30f;
                if (c + 1 > rl0 + 8) sacc[j][3] = -1e30f;
            }
        }
        float rmx0 = -1e30f, rmx1 = -1e30f;
        #pragma unroll
        for (int j = 0; j < 16; j++) {
            rmx0 = fmaxf(rmx0, fmaxf(sacc[j][0], sacc[j][1]));
            rmx1 = fmaxf(rmx1, fmaxf(sacc[j][2], sacc[j][3]));
        }
        rmx0 = fmaxf(rmx0, __shfl_xor_sync(0xffffffffu, rmx0, 1));
        rmx0 = fmaxf(rmx0, __shfl_xor_sync(0xffffffffu, rmx0, 2));
        rmx1 = fmaxf(rmx1, __shfl_xor_sync(0xffffffffu, rmx1, 1));
        rmx1 = fmaxf(rmx1, __shfl_xor_sync(0xffffffffu, rmx1, 2));
        const float mn0 = fmaxf(m0, rmx0), mn1 = fmaxf(m1, rmx1);
        const float rs0 = fast_exp2(m0 - mn0), rs1 = fast_exp2(m1 - mn1);
        m0 = mn0; m1 = mn1;
        float sum0 = 0.f, sum1 = 0.f;
        #pragma unroll
        for (int j = 0; j < 16; j++) {
            sacc[j][0] = fast_exp2(sacc[j][0] - m0);
            sacc[j][1] = fast_exp2(sacc[j][1] - m0);
            sacc[j][2] = fast_exp2(sacc[j][2] - m1);
            sacc[j][3] = fast_exp2(sacc[j][3] - m1);
            sum0 += sacc[j][0] + sacc[j][1];
            sum1 += sacc[j][2] + sacc[j][3];
        }
        sum0 += __shfl_xor_sync(0xffffffffu, sum0, 1);
        sum0 += __shfl_xor_sync(0xffffffffu, sum0, 2);
        sum1 += __shfl_xor_sync(0xffffffffu, sum1, 1);
        sum1 += __shfl_xor_sync(0xffffffffu, sum1, 2);
        l0 = l0 * rs0 + sum0;
        l1 = l1 * rs1 + sum1;
        #pragma unroll
        for (int j = 0; j < 8; j++) {
            oacc[j][0] *= rs0; oacc[j][1] *= rs0;
            oacc[j][2] *= rs1; oacc[j][3] *= rs1;
        }

        // ---- O += P @ V_hi ----
        if (!lastt) CP_WAIT1(); else CP_WAIT0();
        __syncthreads();
        #pragma unroll
        for (int ks = 0; ks < 8; ks++) {
            if (lastt && ks > w) continue;           // P ~ 0 beyond diagonal
            const float* s0 = sacc[2 * ks];
            const float* s1 = sacc[2 * ks + 1];
            uint32_t ph[4];
            ph[0] = packh(s0[0], s0[1]); ph[1] = packh(s0[2], s0[3]);
            ph[2] = packh(s1[0], s1[1]); ph[3] = packh(s1[2], s1[3]);
            #pragma unroll
            for (int p = 0; p < 4; p++) {
                uint32_t vh4[4];
                const uint32_t a = (uint32_t)((ks * 16 + (lane & 15)) * 144
                                 + (p * 16 + (lane >> 4) * 8) * 2);
                ldsm4t(vh4, Vh + a);
                uint32_t bh0[2] = {vh4[0], vh4[1]}, bh1[2] = {vh4[2], vh4[3]};
                mma_f16(oacc[2 * p],     ph, bh0);
                mma_f16(oacc[2 * p + 1], ph, bh1);
            }
        }
        __syncthreads();                 // all warps done reading V smem
        if (!lastt) {
            ldone(Vh, vhg + (size_t)(kb + 1) * 128 * HD);
            CP_COMMIT();
        }
    }

    // ---- epilogue: normalize, write fp16 [B,S,D] ----
    const float inv0 = 1.f / l0, inv1 = 1.f / l1;
    const int b = bh >> 4, h = bh & 15;
    const int s0r = q0 + w * 16 + (lane >> 2);
    const size_t rowA = (size_t)(b * SLEN + s0r);
    const size_t rowB = rowA + 8;
    const int colb = h * 64 + (lane & 3) * 2;
    #pragma unroll
    for (int j = 0; j < 8; j++) {
        const int col = colb + j * 8;
        *(uint32_t*)(g_ah + rowA * DM + col) =
            packh(oacc[j][0] * inv0, oacc[j][1] * inv0);
        *(uint32_t*)(g_ah + rowB * DM + col) =
            packh(oacc[j][2] * inv1, oacc[j][3] * inv1);
    }
}

// ---------------------------------------------------------------------------
extern "C" void kernel_launch(void* const* d_in, const int* in_sizes, int n_in,
                              void* d_out, int out_size)
{
    const float* x    = (const float*)d_in[0];
    const float* rc   = (const float*)d_in[1];
    const float* rs   = (const float*)d_in[2];
    const float* Wqkv = (const float*)d_in[3];
    const float* Wout = (const float*)d_in[4];
    float* out = (float*)d_out;

    const size_t mma_sh   = 4 * GST;     // 73728
    const size_t flash_sh = 4 * FTILE;   // 73728
    cudaFuncSetAttribute(hmma_gemm_kernel<1>,
        cudaFuncAttributeMaxDynamicSharedMemorySize, (int)mma_sh);
    cudaFuncSetAttribute(hmma_gemm_kernel<0>,
        cudaFuncAttributeMaxDynamicSharedMemorySize, (int)mma_sh);
    cudaFuncSetAttribute(flash_hmma_kernel,
        cudaFuncAttributeMaxDynamicSharedMemorySize, (int)flash_sh);

    __half *xh, *ah, *wqh, *wql, *woh, *wol;
    cudaGetSymbolAddress((void**)&xh,  g_xh);
    cudaGetSymbolAddress((void**)&ah,  g_ah);
    cudaGetSymbolAddress((void**)&wqh, g_wqh);
    cudaGetSymbolAddress((void**)&wql, g_wql);
    cudaGetSymbolAddress((void**)&woh, g_woh);
    cudaGetSymbolAddress((void**)&wol, g_wol);

    // 1. converts / transposes
    conv_x_kernel<<<(NROWS * DM) / 1024, 256>>>(x, xh, NROWS * DM);
    conv_wt_kernel<<<dim3(96, 32), 256>>>(Wqkv, wqh, wql, 3 * DM);
    conv_wt_kernel<<<dim3(32, 32), 256>>>(Wout, woh, wol, DM);

    // 2. QKV GEMM (fp16 HMMA) + fused RoPE + scatter
    hmma_gemm_kernel<1><<<dim3(24, 32), 256, mma_sh>>>(
        xh, wqh, wql, rc, rs, nullptr);

    // 3. flash attention (fp16 HMMA) -> g_ah
    flash_hmma_kernel<<<dim3(SLEN / 128, BATCH * NHEAD), 256, flash_sh>>>();

    // 4. out-projection GEMM (fp16 HMMA)
    hmma_gemm_kernel<0><<<dim3(8, 32), 256, mma_sh>>>(
        ah, woh, wol, nullptr, nullptr, out);
}

// round 13
// speedup vs baseline: 1.4188x; 1.2899x over previous
#include <cuda_runtime.h>
#include <cuda_fp16.h>
#include <math.h>
#include <stdint.h>

#define SLEN 2048
#define DM   1024
#define NHEAD 16
#define HD   64
#define BATCH 2
#define NROWS (BATCH*SLEN)   // 4096

// ---------------- scratch (device globals; no allocation allowed) ----------
__device__ __half g_xh[(size_t)NROWS*DM];          // x fp16
__device__ __half g_ah[(size_t)NROWS*DM];          // attn out fp16
__device__ __half g_wqh[(size_t)3*DM*DM];          // W_qkv^T fp16 [3072,1024]
__device__ __half g_woh[(size_t)DM*DM];            // W_out^T fp16
// q/k/v fp16, layout [B*H][S][64]; k keeps lo (B-side of QK)
__device__ __half g_qh[(size_t)BATCH*NHEAD*SLEN*HD];
__device__ __half g_kh[(size_t)BATCH*NHEAD*SLEN*HD];
__device__ __half g_kl[(size_t)BATCH*NHEAD*SLEN*HD];
__device__ __half g_vh[(size_t)BATCH*NHEAD*SLEN*HD];

// ---------------- baseline-PTX helpers -------------------------------------
__device__ __forceinline__ uint32_t smem_u32(const void* p) {
    uint32_t a;
    asm("{ .reg .u64 t; cvta.to.shared.u64 t, %1; cvt.u32.u64 %0, t; }"
        : "=r"(a) : "l"(p));
    return a;
}
__device__ __forceinline__ void cp16(uint32_t s, const void* g) {
    asm volatile("cp.async.cg.shared.global [%0], [%1], 16;"
                 :: "r"(s), "l"(g) : "memory");
}
#define CP_COMMIT() asm volatile("cp.async.commit_group;" ::: "memory")
#define CP_WAIT2()  asm volatile("cp.async.wait_group 2;" ::: "memory")
#define CP_WAIT1()  asm volatile("cp.async.wait_group 1;" ::: "memory")
#define CP_WAIT0()  asm volatile("cp.async.wait_group 0;" ::: "memory")

__device__ __forceinline__ void ldsm4(uint32_t* r, uint32_t addr) {
    asm volatile("ldmatrix.sync.aligned.m8n8.x4.shared.b16 {%0,%1,%2,%3}, [%4];"
        : "=r"(r[0]), "=r"(r[1]), "=r"(r[2]), "=r"(r[3]) : "r"(addr));
}
__device__ __forceinline__ void ldsm4t(uint32_t* r, uint32_t addr) {
    asm volatile("ldmatrix.sync.aligned.m8n8.x4.trans.shared.b16 {%0,%1,%2,%3}, [%4];"
        : "=r"(r[0]), "=r"(r[1]), "=r"(r[2]), "=r"(r[3]) : "r"(addr));
}
// fp16 MMA, fp32 accumulate
__device__ __forceinline__ void mma_f16(float* d, const uint32_t* a,
                                        const uint32_t* b) {
    asm volatile("mma.sync.aligned.m16n8k16.row.col.f32.f16.f16.f32 "
        "{%0,%1,%2,%3}, {%4,%5,%6,%7}, {%8,%9}, {%0,%1,%2,%3};"
        : "+f"(d[0]), "+f"(d[1]), "+f"(d[2]), "+f"(d[3])
        : "r"(a[0]), "r"(a[1]), "r"(a[2]), "r"(a[3]), "r"(b[0]), "r"(b[1]));
}
// pack two fp32 -> half2 (first arg in low half)
__device__ __forceinline__ uint32_t packh(float lo, float hi) {
    __half2 h = __floats2half2_rn(lo, hi);
    return *reinterpret_cast<uint32_t*>(&h);
}

// exp2 via FFMA poly (no MUFU). z expected <= 0; clamped at -40.
__device__ __forceinline__ float fast_exp2(float z) {
    z = fmaxf(z, -40.f);
    const float km = z + 12582912.f;          // round-to-nearest int
    const int   ki = __float_as_int(km) - 0x4B400000;   // = round(z)
    const float f  = z - (km - 12582912.f);   // frac in [-0.5, 0.5]
    float p = 0.0013333558f;
    p = fmaf(p, f, 0.0096181815f);
    p = fmaf(p, f, 0.0555041087f);
    p = fmaf(p, f, 0.2402265069f);
    p = fmaf(p, f, 0.6931471806f);
    p = fmaf(p, f, 1.0f);
    return p * __int_as_float((ki + 127) << 23);
}

#define SCQ   0.18033688011112042f   // hd^-0.5 * log2(e), folded into Q

// ---------------------------------------------------------------------------
// Convert fp32 -> fp16 (activations; single precision level)
// ---------------------------------------------------------------------------
__global__ __launch_bounds__(256) void conv_x_kernel(
    const float* __restrict__ src, __half* __restrict__ dst, int n)
{
    int i = (blockIdx.x * 256 + threadIdx.x) * 4;
    if (i >= n) return;
    float4 v = *(const float4*)(src + i);
    uint2 o;
    o.x = packh(v.x, v.y);
    o.y = packh(v.z, v.w);
    *(uint2*)(dst + i) = o;
}

// ---------------------------------------------------------------------------
// Transpose: W[1024, N] fp32 -> Wt [N, 1024] fp16
// ---------------------------------------------------------------------------
__global__ __launch_bounds__(256) void conv_wt_kernel(
    const float* __restrict__ W, __half* __restrict__ hi, int N)
{
    __shared__ float t[32][33];
    const int n0 = blockIdx.x * 32, k0 = blockIdx.y * 32;
    const int tx = threadIdx.x & 31, ty = threadIdx.x >> 5;
    #pragma unroll
    for (int i = 0; i < 4; i++)
        t[ty + i * 8][tx] = W[(size_t)(k0 + ty + i * 8) * N + n0 + tx];
    __syncthreads();
    #pragma unroll
    for (int i = 0; i < 4; i++) {
        const int n = n0 + ty + i * 8;
        hi[(size_t)n * DM + k0 + tx] = __float2half_rn(t[tx][ty + i * 8]);
    }
}

// ---------------------------------------------------------------------------
// HMMA pure-fp16 GEMM: D = A * B^T, 128x128 CTA tile, 8 warps (4m x 2n),
// m16n8k16, K-chunk 32, 4-stage single-sync cp.async pipeline.
// Stage = 2 arrays x 128 rows x 80B = 20480B; 4 stages = 80KB -> 2 CTAs/SM.
// DO_QKV: fused RoPE + fp16 scatter (q,v hi; k hi+lo).
// ---------------------------------------------------------------------------
#define GST   20480
#define GARR  10240
template<int DO_QKV>
__global__ __launch_bounds__(256, 2) void hmma_gemm_kernel(
    const __half* __restrict__ A, const __half* __restrict__ B,
    const float* __restrict__ rc, const float* __restrict__ rs,
    float* __restrict__ outp)
{
    extern __shared__ char smem[];
    const uint32_t sb = smem_u32(smem);
    const int tid = threadIdx.x, lane = tid & 31, wid = tid >> 5;
    const int wm = wid >> 1, wn = wid & 1;
    const int row0 = blockIdx.y * 128, col0 = blockIdx.x * 128;

    float acc[2][8][4];
    #pragma unroll
    for (int m = 0; m < 2; m++)
        #pragma unroll
        for (int n = 0; n < 8; n++)
            #pragma unroll
            for (int q = 0; q < 4; q++) acc[m][n][q] = 0.f;

    const int lrow = tid >> 1, kh = tid & 1;
    const __half* ga0 = A + (size_t)(row0 + lrow) * DM + kh * 16;
    const __half* ga1 = B + (size_t)(col0 + lrow) * DM + kh * 16;
    const uint32_t ldst = lrow * 80 + kh * 32;

    auto issue = [&](int c) {
        const uint32_t buf = sb + (c & 3) * GST;
        const int k0 = c * 32;
        cp16(buf + ldst,             ga0 + k0);
        cp16(buf + ldst + 16,        ga0 + k0 + 8);
        cp16(buf + GARR + ldst,      ga1 + k0);
        cp16(buf + GARR + ldst + 16, ga1 + k0 + 8);
    };

    issue(0); CP_COMMIT();
    issue(1); CP_COMMIT();
    issue(2); CP_COMMIT();

    const uint32_t aoff = (uint32_t)((wm * 32 + (lane & 15)) * 80
                        + (lane >> 4) * 16);
    const uint32_t boff = (uint32_t)(GARR
                        + (wn * 64 + (lane & 7) + ((lane >> 4) << 3)) * 80
                        + ((lane >> 3) & 1) * 16);

    for (int c = 0; c < 32; c++) {
        CP_WAIT2();
        __syncthreads();
        if (c + 3 < 32) issue(c + 3);
        CP_COMMIT();
        const uint32_t buf = sb + (c & 3) * GST;
        const uint32_t ab = buf + aoff;
        const uint32_t bb = buf + boff;
        #pragma unroll
        for (int ks = 0; ks < 2; ks++) {
            uint32_t ah[2][4];
            ldsm4(ah[0], ab + ks * 32);
            ldsm4(ah[1], ab + 16 * 80 + ks * 32);
            #pragma unroll
            for (int nf2 = 0; nf2 < 4; nf2++) {
                uint32_t bh4[4];
                ldsm4(bh4, bb + nf2 * 16 * 80 + ks * 32);
                #pragma unroll
                for (int mt = 0; mt < 2; mt++) {
                    mma_f16(acc[mt][2 * nf2],     ah[mt], bh4);
                    mma_f16(acc[mt][2 * nf2 + 1], ah[mt], bh4 + 2);
                }
            }
        }
    }

    // ---------------- epilogue ----------------
    const int l4 = lane >> 2, l2 = (lane & 3) * 2;
    if (DO_QKV) {
        const int part = col0 >> 10;                 // 0=q, 1=k, 2=v
        const int head = ((col0 & 1023) >> 6) + wn;
        __half* dhi = (part == 0) ? g_qh : (part == 1) ? g_kh : g_vh;
        #pragma unroll
        for (int mt = 0; mt < 2; mt++) {
            #pragma unroll
            for (int rr = 0; rr < 2; rr++) {
                const int grow = row0 + wm * 32 + mt * 16 + l4 + rr * 8;
                const int b = grow >> 11, s = grow & 2047;
                const size_t obase = ((size_t)(b * NHEAD + head) * SLEN + s) * HD;
                const float* rcp = rc + s * 32;
                const float* rsp = rs + s * 32;
                #pragma unroll
                for (int nf = 0; nf < 8; nf++) {
                    const int d = nf * 8 + l2;
                    const float v1 = acc[mt][nf][rr * 2 + 0];
                    const float v2 = acc[mt][nf][rr * 2 + 1];
                    float ox, oy;
                    if (part < 2) {
                        const int pi = d >> 1;
                        const float cth = rcp[pi], sth = rsp[pi];
                        ox = v1 * cth - v2 * sth;
                        oy = v1 * sth + v2 * cth;
                    } else {
                        ox = v1; oy = v2;
                    }
                    if (part == 1) {
                        const uint32_t hb = packh(ox, oy);
                        const __half2 h2 = *reinterpret_cast<const __half2*>(&hb);
                        const uint32_t lb = packh(ox - __half2float(__low2half(h2)),
                                                  oy - __half2float(__high2half(h2)));
                        *(uint32_t*)(dhi + obase + d) = hb;
                        *(uint32_t*)(g_kl + obase + d) = lb;
                    } else {
                        if (part == 0) { ox *= SCQ; oy *= SCQ; }
                        *(uint32_t*)(dhi + obase + d) = packh(ox, oy);
                    }
                }
            }
        }
    } else {
        #pragma unroll
        for (int mt = 0; mt < 2; mt++) {
            #pragma unroll
            for (int rr = 0; rr < 2; rr++) {
                const int grow = row0 + wm * 32 + mt * 16 + l4 + rr * 8;
                float* op = outp + (size_t)grow * DM + col0 + wn * 64 + l2;
                #pragma unroll
                for (int nf = 0; nf < 8; nf++) {
                    float2 o;
                    o.x = acc[mt][nf][rr * 2 + 0];
                    o.y = acc[mt][nf][rr * 2 + 1];
                    *(float2*)(op + nf * 8) = o;
                }
            }
        }
    }
}

// ---------------------------------------------------------------------------
// HMMA fp16 FlashAttention: BM=128 queries, KN=128 keys/tile, 256 thr.
// QK: q @ (k_hi + k_lo) (2 MMAs). PV: p @ v_hi (1 MMA). FFMA exp2 softmax;
// P stays in registers. Diagonal-tile skips (exact).
// smem: 4 tiles (Q, Kh, Kl, Vh) of 128 x 72 fp16 (144B stride).
// ---------------------------------------------------------------------------
#define FTILE 18432          // 128*72*2 bytes
__global__ __launch_bounds__(256) void flash_hmma_kernel()
{
    extern __shared__ char fsm[];
    const uint32_t sb = smem_u32(fsm);
    const uint32_t Qt = sb;
    const uint32_t Kh = sb + 1 * FTILE, Kl = sb + 2 * FTILE;
    const uint32_t Vh = sb + 3 * FTILE;

    const int tid = threadIdx.x, lane = tid & 31, w = tid >> 5;
    const int qb = gridDim.x - 1 - blockIdx.x;      // long CTAs first
    const int q0 = qb * 128, bh = blockIdx.y;
    const size_t base = (size_t)bh * SLEN * HD;

    const __half *qg  = g_qh + base + (size_t)q0 * HD;
    const __half *khg = g_kh + base, *klg = g_kl + base;
    const __half *vhg = g_vh + base;

    auto ldpair = [&](uint32_t dh, uint32_t dl,
                      const __half* gh, const __half* gl) {
        #pragma unroll
        for (int kk = 0; kk < 4; kk++) {
            const int c = tid + kk * 256;
            const int row = c >> 3, q8 = c & 7;
            cp16(dh + row * 144 + q8 * 16, gh + row * 64 + q8 * 8);
            cp16(dl + row * 144 + q8 * 16, gl + row * 64 + q8 * 8);
        }
    };
    auto ldone = [&](uint32_t d, const __half* g) {
        #pragma unroll
        for (int kk = 0; kk < 4; kk++) {
            const int c = tid + kk * 256;
            const int row = c >> 3, q8 = c & 7;
            cp16(d + row * 144 + q8 * 16, g + row * 64 + q8 * 8);
        }
    };

    ldone(Qt, qg);
    ldpair(Kh, Kl, khg, klg);
    CP_COMMIT();
    ldone(Vh, vhg);
    CP_COMMIT();

    uint32_t qf[4][4];
    float oacc[8][4];
    #pragma unroll
    for (int j = 0; j < 8; j++)
        #pragma unroll
        for (int q = 0; q < 4; q++) oacc[j][q] = 0.f;
    float m0 = -1e30f, m1 = -1e30f, l0 = 0.f, l1 = 0.f;

    const int nkb = qb + 1;
    for (int kb = 0; kb < nkb; kb++) {
        const bool lastt = (kb == nkb - 1);
        CP_WAIT1();
        __syncthreads();
        if (kb == 0) {
            #pragma unroll
            for (int ks = 0; ks < 4; ks++) {
                const uint32_t a = (uint32_t)((w * 16 + (lane & 15)) * 144
                                 + (ks * 16 + (lane >> 4) * 8) * 2);
                ldsm4(qf[ks], Qt + a);
            }
        }
        // ---- S = Q @ (K_hi + K_lo)^T ----
        float sacc[16][4];
        #pragma unroll
        for (int j = 0; j < 16; j++)
            #pragma unroll
            for (int q = 0; q < 4; q++) sacc[j][q] = 0.f;
        #pragma unroll
        for (int ks = 0; ks < 4; ks++) {
            #pragma unroll
            for (int p = 0; p < 8; p++) {
                if (lastt && p > w) continue;        // fully-masked col group
                uint32_t kh4[4], kl4[4];
                const uint32_t a = (uint32_t)((p * 16 + (lane & 15)) * 144
                                 + (ks * 16 + (lane >> 4) * 8) * 2);
                ldsm4(kh4, Kh + a);
                ldsm4(kl4, Kl + a);
                uint32_t bh0[2] = {kh4[0], kh4[2]}, bh1[2] = {kh4[1], kh4[3]};
                uint32_t bl0[2] = {kl4[0], kl4[2]}, bl1[2] = {kl4[1], kl4[3]};
                mma_f16(sacc[2 * p],     qf[ks], bh0);
                mma_f16(sacc[2 * p],     qf[ks], bl0);
                mma_f16(sacc[2 * p + 1], qf[ks], bh1);
                mma_f16(sacc[2 * p + 1], qf[ks], bl1);
            }
        }
        __syncthreads();                 // all warps done reading K smem
        if (!lastt) {
            ldpair(Kh, Kl, khg + (size_t)(kb + 1) * 128 * HD,
                           klg + (size_t)(kb + 1) * 128 * HD);
            CP_COMMIT();
        }

        // ---- softmax (registers only; overlaps with K prefetch) ----
        if (lastt) {  // diagonal tile: mask col > row (tile-local, kb*128==q0)
            const int rl0 = w * 16 + (lane >> 2);
            #pragma unroll
            for (int j = 0; j < 16; j++) {
                const int c = j * 8 + (lane & 3) * 2;
                if (c     > rl0)     sacc[j][0] = -1e30f;
                if (c + 1 > rl0)     sacc[j][1] = -1e30f;
                if (c     > rl0 + 8) sacc[j][2] = -1e30f;
                if (c + 1 > rl0 + 8) sacc[j][3] = -1e30f;
            }
        }
        float rmx0 = -1e30f, rmx1 = -1e30f;
        #pragma unroll
        for (int j = 0; j < 16; j++) {
            rmx0 = fmaxf(rmx0, fmaxf(sacc[j][0], sacc[j][1]));
            rmx1 = fmaxf(rmx1, fmaxf(sacc[j][2], sacc[j][3]));
        }
        rmx0 = fmaxf(rmx0, __shfl_xor_sync(0xffffffffu, rmx0, 1));
        rmx0 = fmaxf(rmx0, __shfl_xor_sync(0xffffffffu, rmx0, 2));
        rmx1 = fmaxf(rmx1, __shfl_xor_sync(0xffffffffu, rmx1, 1));
        rmx1 = fmaxf(rmx1, __shfl_xor_sync(0xffffffffu, rmx1, 2));
        const float mn0 = fmaxf(m0, rmx0), mn1 = fmaxf(m1, rmx1);
        const float rs0 = fast_exp2(m0 - mn0), rs1 = fast_exp2(m1 - mn1);
        m0 = mn0; m1 = mn1;
        float sum0 = 0.f, sum1 = 0.f;
        #pragma unroll
        for (int j = 0; j < 16; j++) {
            sacc[j][0] = fast_exp2(sacc[j][0] - m0);
            sacc[j][1] = fast_exp2(sacc[j][1] - m0);
            sacc[j][2] = fast_exp2(sacc[j][2] - m1);
            sacc[j][3] = fast_exp2(sacc[j][3] - m1);
            sum0 += sacc[j][0] + sacc[j][1];
            sum1 += sacc[j][2] + sacc[j][3];
        }
        sum0 += __shfl_xor_sync(0xffffffffu, sum0, 1);
        sum0 += __shfl_xor_sync(0xffffffffu, sum0, 2);
        sum1 += __shfl_xor_sync(0xffffffffu, sum1, 1);
        sum1 += __shfl_xor_sync(0xffffffffu, sum1, 2);
        l0 = l0 * rs0 + sum0;
        l1 = l1 * rs1 + sum1;
        #pragma unroll
        for (int j = 0; j < 8; j++) {
            oacc[j][0] *= rs0; oacc[j][1] *= rs0;
            oacc[j][2] *= rs1; oacc[j][3] *= rs1;
        }

        // ---- O += P @ V_hi ----
        if (!lastt) CP_WAIT1(); else CP_WAIT0();
        __syncthreads();
        #pragma unroll
        for (int ks = 0; ks < 8; ks++) {
            if (lastt && ks > w) continue;           // P ~ 0 beyond diagonal
            const float* s0 = sacc[2 * ks];
            const float* s1 = sacc[2 * ks + 1];
            uint32_t ph[4];
            ph[0] = packh(s0[0], s0[1]); ph[1] = packh(s0[2], s0[3]);
            ph[2] = packh(s1[0], s1[1]); ph[3] = packh(s1[2], s1[3]);
            #pragma unroll
            for (int p = 0; p < 4; p++) {
                uint32_t vh4[4];
                const uint32_t a = (uint32_t)((ks * 16 + (lane & 15)) * 144
                                 + (p * 16 + (lane >> 4) * 8) * 2);
                ldsm4t(vh4, Vh + a);
                uint32_t bh0[2] = {vh4[0], vh4[1]}, bh1[2] = {vh4[2], vh4[3]};
                mma_f16(oacc[2 * p],     ph, bh0);
                mma_f16(oacc[2 * p + 1], ph, bh1);
            }
        }
        __syncthreads();                 // all warps done reading V smem
        if (!lastt) {
            ldone(Vh, vhg + (size_t)(kb + 1) * 128 * HD);
            CP_COMMIT();
        }
    }

    // ---- epilogue: normalize, write fp16 [B,S,D] ----
    const float inv0 = 1.f / l0, inv1 = 1.f / l1;
    const int b = bh >> 4, h = bh & 15;
    const int s0r = q0 + w * 16 + (lane >> 2);
    const size_t rowA = (size_t)(b * SLEN + s0r);
    const size_t rowB = rowA + 8;
    const int colb = h * 64 + (lane & 3) * 2;
    #pragma unroll
    for (int j = 0; j < 8; j++) {
        const int col = colb + j * 8;
        *(uint32_t*)(g_ah + rowA * DM + col) =
            packh(oacc[j][0] * inv0, oacc[j][1] * inv0);
        *(uint32_t*)(g_ah + rowB * DM + col) =
            packh(oacc[j][2] * inv1, oacc[j][3] * inv1);
    }
}

// ---------------------------------------------------------------------------
extern "C" void kernel_launch(void* const* d_in, const int* in_sizes, int n_in,
                              void* d_out, int out_size)
{
    const float* x    = (const float*)d_in[0];
    const float* rc   = (const float*)d_in[1];
    const float* rs   = (const float*)d_in[2];
    const float* Wqkv = (const float*)d_in[3];
    const float* Wout = (const float*)d_in[4];
    float* out = (float*)d_out;

    const size_t mma_sh   = 4 * GST;     // 81920
    const size_t flash_sh = 4 * FTILE;   // 73728
    cudaFuncSetAttribute(hmma_gemm_kernel<1>,
        cudaFuncAttributeMaxDynamicSharedMemorySize, (int)mma_sh);
    cudaFuncSetAttribute(hmma_gemm_kernel<0>,
        cudaFuncAttributeMaxDynamicSharedMemorySize, (int)mma_sh);
    cudaFuncSetAttribute(flash_hmma_kernel,
        cudaFuncAttributeMaxDynamicSharedMemorySize, (int)flash_sh);

    __half *xh, *ah, *wqh, *woh;
    cudaGetSymbolAddress((void**)&xh,  g_xh);
    cudaGetSymbolAddress((void**)&ah,  g_ah);
    cudaGetSymbolAddress((void**)&wqh, g_wqh);
    cudaGetSymbolAddress((void**)&woh, g_woh);

    // 1. converts / transposes
    conv_x_kernel<<<(NROWS * DM) / 1024, 256>>>(x, xh, NROWS * DM);
    conv_wt_kernel<<<dim3(96, 32), 256>>>(Wqkv, wqh, 3 * DM);
    conv_wt_kernel<<<dim3(32, 32), 256>>>(Wout, woh, DM);

    // 2. QKV GEMM (fp16 HMMA) + fused RoPE + scatter
    hmma_gemm_kernel<1><<<dim3(24, 32), 256, mma_sh>>>(
        xh, wqh, rc, rs, nullptr);

    // 3. flash attention (fp16 HMMA) -> g_ah
    flash_hmma_kernel<<<dim3(SLEN / 128, BATCH * NHEAD), 256, flash_sh>>>();

    // 4. out-projection GEMM (fp16 HMMA)
    hmma_gemm_kernel<0><<<dim3(8, 32), 256, mma_sh>>>(
        ah, woh, nullptr, nullptr, out);
}